// round 15
// baseline (speedup 1.0000x reference)
#include <cuda_runtime.h>
#include <cuda_bf16.h>
#include <cstdint>

// AttentionLayer: B=2048, F=128, E=64, H=4, A=64
//   out[b,f,h*64+a] = relu( softmax(q k^T) v + (feature @ res_w)[:, h*64:] )
//
// R13: algebraic fold S = f·(Wq·Wk^T)·f^T. A prep kernel computes M = Wq·Wk^T
// in exact fp32 per head and pre-converts M / Wv / res_w-slice into hi/lo bf16
// tiles (smem-layout-identical). Main kernel: 4 GEMMs instead of 5
// (qm = f·M, v = f·Wv, S = qm·f^T, em = P·v, res = f·R), all 3-term hi/lo
// emulated fp32 on mma.sync. 1 CTA per (b,h), 256 threads.

#define B_ 2048
#define F_ 128
#define E_ 64
#define H_ 4
#define A_ 64

// ---------------- smem layout (bytes); bf16 tiles, row stride 144 B --------
#define SM_FH   0        // f [g][e] 128x64, stride 144 (B operand of S; frag src)
#define SM_FL   18432
#define SM_MH   36864    // M tile [e][a] 64x64   } contiguous 55296B block
#define SM_ML   46080    //                        } copied raw from g_wt[h]
#define SM_WVH  55296    // Wv tile [e][a]
#define SM_WVL  64512
#define SM_RH   73728    // res_w slice tile [e][a]
#define SM_RL   82944
#define SM_VH   92160    // v [g][a] 128x64
#define SM_VL   110592
#define SMEM_BYTES 129024

// Pre-converted weight tiles: per head [MH][ML][WVH][WVL][RH][RL], 6*9216 B.
__device__ uint4 g_wt[H_][3456];

// ---------------- PTX helpers ----------------------------------------------
__device__ __forceinline__ uint32_t smem_u32(const void* p) {
    uint32_t a;
    asm("{ .reg .u64 t; cvta.to.shared.u64 t, %1; cvt.u32.u64 %0, t; }"
        : "=r"(a) : "l"(p));
    return a;
}
__device__ __forceinline__ void ldsm4(uint32_t addr, uint32_t r[4]) {
    asm volatile("ldmatrix.sync.aligned.m8n8.x4.shared.b16 {%0,%1,%2,%3}, [%4];"
                 : "=r"(r[0]), "=r"(r[1]), "=r"(r[2]), "=r"(r[3]) : "r"(addr));
}
__device__ __forceinline__ void ldsm4t(uint32_t addr, uint32_t r[4]) {
    asm volatile("ldmatrix.sync.aligned.m8n8.x4.trans.shared.b16 {%0,%1,%2,%3}, [%4];"
                 : "=r"(r[0]), "=r"(r[1]), "=r"(r[2]), "=r"(r[3]) : "r"(addr));
}
// non-volatile: register dataflow expresses dependencies; ptxas may reorder.
__device__ __forceinline__ void mma16816(float d[4], const uint32_t a[4],
                                         uint32_t b0, uint32_t b1) {
    asm("mma.sync.aligned.m16n8k16.row.col.f32.bf16.bf16.f32 "
        "{%0,%1,%2,%3}, {%4,%5,%6,%7}, {%8,%9}, {%0,%1,%2,%3};"
        : "+f"(d[0]), "+f"(d[1]), "+f"(d[2]), "+f"(d[3])
        : "r"(a[0]), "r"(a[1]), "r"(a[2]), "r"(a[3]), "r"(b0), "r"(b1));
}
__device__ __forceinline__ void mma3(float dA[4], float dB[4],
                                     const uint32_t ah[4], const uint32_t al[4],
                                     const uint32_t bh[4], const uint32_t bl[4]) {
    mma16816(dA, ah, bh[0], bh[1]);
    mma16816(dB, ah, bh[2], bh[3]);
    mma16816(dA, ah, bl[0], bl[1]);
    mma16816(dB, ah, bl[2], bl[3]);
    mma16816(dA, al, bh[0], bh[1]);
    mma16816(dB, al, bh[2], bh[3]);
}

// packed conversion: cvt.rn.bf16x2.f32 (first operand -> high half)
__device__ __forceinline__ uint32_t cvt_bf2(float lo_val, float hi_val) {
    uint32_t r;
    asm("cvt.rn.bf16x2.f32 %0, %1, %2;" : "=r"(r) : "f"(hi_val), "f"(lo_val));
    return r;
}
// hi/lo split of (a,b): returns packed hi pair (a in low half), writes packed lo.
__device__ __forceinline__ uint32_t pack_hilo(float a, float b, uint32_t& lo) {
    uint32_t hi = cvt_bf2(a, b);
    float ha = __uint_as_float(hi << 16);            // bf16 -> f32 exact
    float hb = __uint_as_float(hi & 0xFFFF0000u);
    lo = cvt_bf2(a - ha, b - hb);
    return hi;
}

// =================== prep kernel: M = Wq Wk^T + tile conversion =============
__global__ __launch_bounds__(256)
void prep_kernel(const float* __restrict__ Qw, const float* __restrict__ Kw,
                 const float* __restrict__ Vw, const float* __restrict__ res_w) {
    __shared__ float swq[64 * 65];   // padded rows: bank-conflict-free
    __shared__ float swk[64 * 65];
    const int h = blockIdx.x, t = threadIdx.x;
    uint8_t* dst = (uint8_t*)g_wt[h];

    for (int i = t; i < 64 * 64; i += 256) {
        int r = i >> 6, c = i & 63;
        swq[r * 65 + c] = Qw[h * 4096 + i];
        swk[r * 65 + c] = Kw[h * 4096 + i];
    }
    __syncthreads();

    // M[e][a0..a0+15]: 4 threads per e-row, 16 a-columns each.
    {
        const int e = t >> 2, a0 = (t & 3) * 16;
        float acc[16];
        #pragma unroll
        for (int c = 0; c < 16; c++) acc[c] = 0.f;
        for (int j = 0; j < 64; j++) {
            float qe = swq[e * 65 + j];
            #pragma unroll
            for (int c = 0; c < 16; c++)
                acc[c] = fmaf(qe, swk[(a0 + c) * 65 + j], acc[c]);
        }
        #pragma unroll
        for (int c = 0; c < 8; c++) {
            uint32_t lo, hi = pack_hilo(acc[2 * c], acc[2 * c + 1], lo);
            uint32_t off = (uint32_t)(e * 144 + (a0 + 2 * c) * 2);
            *(uint32_t*)(dst + 0    + off) = hi;
            *(uint32_t*)(dst + 9216 + off) = lo;
        }
    }
    // Wv tile [e][a]
    for (int pi = t; pi < 2048; pi += 256) {
        int e = pi >> 5, a = (pi & 31) * 2;
        float2 v = *(const float2*)(Vw + h * 4096 + e * 64 + a);
        uint32_t lo, hi = pack_hilo(v.x, v.y, lo);
        uint32_t off = (uint32_t)(e * 144 + a * 2);
        *(uint32_t*)(dst + 18432 + off) = hi;
        *(uint32_t*)(dst + 27648 + off) = lo;
    }
    // res_w slice [e][h*64+a]
    for (int pi = t; pi < 2048; pi += 256) {
        int e = pi >> 5, a = (pi & 31) * 2;
        float2 v = *(const float2*)(res_w + e * 256 + h * 64 + a);
        uint32_t lo, hi = pack_hilo(v.x, v.y, lo);
        uint32_t off = (uint32_t)(e * 144 + a * 2);
        *(uint32_t*)(dst + 36864 + off) = hi;
        *(uint32_t*)(dst + 46080 + off) = lo;
    }
}

// =================== main kernel ============================================
__global__ __launch_bounds__(256, 1)
void attn_mma_kernel(const float* __restrict__ feature,
                     float* __restrict__ out) {
    extern __shared__ char smem[];
    const uint32_t sb = smem_u32(smem);
    const int t = threadIdx.x;
    const int w = t >> 5, l = t & 31;
    const int grp = l >> 2, qt = l & 3;      // C/A-fragment coords
    const int lr = l & 7, lm = l >> 3;       // ldmatrix lane coords
    const int b = blockIdx.x >> 2, h = blockIdx.x & 3;
    const int r0 = w * 16;                   // warp's output row base

    // ======== Phase 0: f -> smem hi/lo tile; weight tiles raw copy =========
    {
        const float4* fg = (const float4*)(feature + (size_t)b * (F_ * E_));
        #pragma unroll
        for (int it = 0; it < 8; it++) {
            int i = t + it * 256;
            float4 v = fg[i];
            int row = i >> 4, c4 = (i & 15) << 2;
            uint32_t lo0, lo1;
            uint32_t h0 = pack_hilo(v.x, v.y, lo0);
            uint32_t h1 = pack_hilo(v.z, v.w, lo1);
            uint32_t off = (uint32_t)(row * 144 + (c4 << 1));
            *(uint2*)(smem + SM_FH + off) = make_uint2(h0, h1);
            *(uint2*)(smem + SM_FL + off) = make_uint2(lo0, lo1);
        }
        const uint4* src = g_wt[h];
        uint4* dstw = (uint4*)(smem + SM_MH);
        #pragma unroll 2
        for (int i = t; i < 3456; i += 256) dstw[i] = src[i];
    }
    __syncthreads();

    // ======== Phase 0c: f A-fragments from smem (R8-verified A-path) =======
    uint32_t fh[4][4], fl[4][4];
    #pragma unroll
    for (int ks = 0; ks < 4; ks++) {
        uint32_t a_rel = (uint32_t)((r0 + lr + ((lm & 1) << 3)) * 144 +
                                    (ks << 5) + ((lm >> 1) << 4));
        ldsm4(sb + SM_FH + a_rel, fh[ks]);
        ldsm4(sb + SM_FL + a_rel, fl[ks]);
    }

    // GEMM with register A-frags (4 k-chunks), B from smem [K=64][N=64] (.trans)
    auto gemmA = [&](const uint32_t ah[4][4], const uint32_t al[4][4],
                     uint32_t bh_off, uint32_t bl_off, float acc[8][4]) {
        #pragma unroll
        for (int ks = 0; ks < 4; ks++) {
            #pragma unroll
            for (int p = 0; p < 4; p++) {
                uint32_t b_rel = (uint32_t)(((ks << 4) + lr + ((lm & 1) << 3)) * 144 +
                                            (p << 5) + ((lm >> 1) << 4));
                uint32_t bh[4], bl[4];
                ldsm4t(sb + bh_off + b_rel, bh);
                ldsm4t(sb + bl_off + b_rel, bl);
                mma3(acc[2 * p], acc[2 * p + 1], ah[ks], al[ks], bh, bl);
            }
        }
    };
    // C-frag -> A-frag conversion (hi/lo split), 4 k-chunks from 8 col-tiles
    auto to_frag4 = [&](const float acc[8][4], uint32_t oh[4][4], uint32_t ol[4][4]) {
        #pragma unroll
        for (int ks = 0; ks < 4; ks++) {
            oh[ks][0] = pack_hilo(acc[2 * ks][0],     acc[2 * ks][1],     ol[ks][0]);
            oh[ks][1] = pack_hilo(acc[2 * ks][2],     acc[2 * ks][3],     ol[ks][1]);
            oh[ks][2] = pack_hilo(acc[2 * ks + 1][0], acc[2 * ks + 1][1], ol[ks][2]);
            oh[ks][3] = pack_hilo(acc[2 * ks + 1][2], acc[2 * ks + 1][3], ol[ks][3]);
        }
    };
    // store C tile (16 rows x 64 cols) to smem as bf16 hi/lo, stride 144
    auto store_hilo = [&](const float acc[8][4], int oh, int ol) {
        #pragma unroll
        for (int i = 0; i < 8; i++) {
            int cbyte = (((i << 3) + (qt << 1)) << 1);
            uint32_t lo;
            uint32_t hi = pack_hilo(acc[i][0], acc[i][1], lo);
            *(uint32_t*)(smem + oh + (r0 + grp) * 144 + cbyte) = hi;
            *(uint32_t*)(smem + ol + (r0 + grp) * 144 + cbyte) = lo;
            hi = pack_hilo(acc[i][2], acc[i][3], lo);
            *(uint32_t*)(smem + oh + (r0 + grp + 8) * 144 + cbyte) = hi;
            *(uint32_t*)(smem + ol + (r0 + grp + 8) * 144 + cbyte) = lo;
        }
    };

    // ================= Phase 1: qm = f@M,  v = f@Wv ========================
    uint32_t qmh[4][4], qml[4][4];
    {
        float acc[8][4] = {};
        gemmA(fh, fl, SM_MH, SM_ML, acc);
        to_frag4(acc, qmh, qml);             // qm stays in registers
    }
    {
        float acc[8][4] = {};
        gemmA(fh, fl, SM_WVH, SM_WVL, acc);
        store_hilo(acc, SM_VH, SM_VL);       // v needed by all warps -> smem
    }
    __syncthreads();

    // ================= Phase 2: S = qm @ f^T (16 x 128 per warp) ===========
    float sacc[16][4] = {};
    #pragma unroll
    for (int ks = 0; ks < 4; ks++) {
        #pragma unroll
        for (int p = 0; p < 8; p++) {
            uint32_t b_rel = (uint32_t)(((p << 4) + lr + ((lm >> 1) << 3)) * 144 +
                                        (ks << 5) + ((lm & 1) << 4));
            uint32_t bh[4], bl[4];
            ldsm4(sb + SM_FH + b_rel, bh);
            ldsm4(sb + SM_FL + b_rel, bl);
            mma3(sacc[2 * p], sacc[2 * p + 1], qmh[ks], qml[ks], bh, bl);
        }
    }

    // ================= Phase 3: softmax in registers =======================
    float invA, invB;
    {
        float mA = -3.402823466e38f, mB = -3.402823466e38f;
        #pragma unroll
        for (int i = 0; i < 16; i++) {
            mA = fmaxf(mA, fmaxf(sacc[i][0], sacc[i][1]));
            mB = fmaxf(mB, fmaxf(sacc[i][2], sacc[i][3]));
        }
        mA = fmaxf(mA, __shfl_xor_sync(0xFFFFFFFFu, mA, 1));
        mA = fmaxf(mA, __shfl_xor_sync(0xFFFFFFFFu, mA, 2));
        mB = fmaxf(mB, __shfl_xor_sync(0xFFFFFFFFu, mB, 1));
        mB = fmaxf(mB, __shfl_xor_sync(0xFFFFFFFFu, mB, 2));
        float sA = 0.f, sB = 0.f;
        #pragma unroll
        for (int i = 0; i < 16; i++) {
            sacc[i][0] = __expf(sacc[i][0] - mA);
            sacc[i][1] = __expf(sacc[i][1] - mA);
            sacc[i][2] = __expf(sacc[i][2] - mB);
            sacc[i][3] = __expf(sacc[i][3] - mB);
            sA += sacc[i][0] + sacc[i][1];
            sB += sacc[i][2] + sacc[i][3];
        }
        sA += __shfl_xor_sync(0xFFFFFFFFu, sA, 1);
        sA += __shfl_xor_sync(0xFFFFFFFFu, sA, 2);
        sB += __shfl_xor_sync(0xFFFFFFFFu, sB, 1);
        sB += __shfl_xor_sync(0xFFFFFFFFu, sB, 2);
        invA = 1.0f / sA;
        invB = 1.0f / sB;
    }

    // P (unnormalized) -> register A-fragments, 8 k-chunks
    uint32_t ph[8][4], pl[8][4];
    #pragma unroll
    for (int ks = 0; ks < 8; ks++) {
        ph[ks][0] = pack_hilo(sacc[2 * ks][0],     sacc[2 * ks][1],     pl[ks][0]);
        ph[ks][1] = pack_hilo(sacc[2 * ks][2],     sacc[2 * ks][3],     pl[ks][1]);
        ph[ks][2] = pack_hilo(sacc[2 * ks + 1][0], sacc[2 * ks + 1][1], pl[ks][2]);
        ph[ks][3] = pack_hilo(sacc[2 * ks + 1][2], sacc[2 * ks + 1][3], pl[ks][3]);
    }

    // ================= Phase 4: em = P @ v  (K=128) ========================
    float eacc[8][4] = {};
    #pragma unroll
    for (int ks = 0; ks < 8; ks++) {
        #pragma unroll
        for (int p = 0; p < 4; p++) {
            uint32_t b_rel = (uint32_t)(((ks << 4) + lr + ((lm & 1) << 3)) * 144 +
                                        (p << 5) + ((lm >> 1) << 4));
            uint32_t bh[4], bl[4];
            ldsm4t(sb + SM_VH + b_rel, bh);
            ldsm4t(sb + SM_VL + b_rel, bl);
            mma3(eacc[2 * p], eacc[2 * p + 1], ph[ks], pl[ks], bh, bl);
        }
    }

    // ================= Phase 5: res = f @ res_w slice ======================
    float racc[8][4] = {};
    gemmA(fh, fl, SM_RH, SM_RL, racc);

    // ================= Phase 6: epilogue relu(em/sum + res) ================
    {
        #pragma unroll
        for (int i = 0; i < 8; i++) {
            int c = h * A_ + (i << 3) + (qt << 1);
            float2 o;
            o.x = fmaxf(fmaf(eacc[i][0], invA, racc[i][0]), 0.f);
            o.y = fmaxf(fmaf(eacc[i][1], invA, racc[i][1]), 0.f);
            *(float2*)(out + ((size_t)(b * F_) + r0 + grp) * (H_ * A_) + c) = o;
            o.x = fmaxf(fmaf(eacc[i][2], invB, racc[i][2]), 0.f);
            o.y = fmaxf(fmaf(eacc[i][3], invB, racc[i][3]), 0.f);
            *(float2*)(out + ((size_t)(b * F_) + r0 + grp + 8) * (H_ * A_) + c) = o;
        }
    }
}

extern "C" void kernel_launch(void* const* d_in, const int* in_sizes, int n_in,
                              void* d_out, int out_size) {
    const float* feature = (const float*)d_in[0];
    const float* Qw      = (const float*)d_in[1];
    const float* Kw      = (const float*)d_in[2];
    const float* Vw      = (const float*)d_in[3];
    const float* res_w   = (const float*)d_in[4];
    float* out = (float*)d_out;

    prep_kernel<<<H_, 256>>>(Qw, Kw, Vw, res_w);

    cudaFuncSetAttribute(attn_mma_kernel,
                         cudaFuncAttributeMaxDynamicSharedMemorySize, SMEM_BYTES);
    attn_mma_kernel<<<B_ * H_, 256, SMEM_BYTES>>>(feature, out);
}

// round 16
// speedup vs baseline: 1.0138x; 1.0138x over previous
#include <cuda_runtime.h>
#include <cuda_bf16.h>
#include <cstdint>

// AttentionLayer: B=2048, F=128, E=64, H=4, A=64
//   out[b,f,h*64+a] = relu( softmax(q k^T) v + (feature @ res_w)[:, h*64:] )
//
// R16: R13 fold (S = f·(WqWk^T)·f^T via prep kernel) + 4-way accumulator
// interleaving in all GEMM phases (12 MMAs round-robin over 4 independent
// accumulators per B-pair) to break the HMMA D->D dependency stalls.
// f A-frags are scoped (not persistent) to keep regs under the 255 cap.

#define B_ 2048
#define F_ 128
#define E_ 64
#define H_ 4
#define A_ 64

// ---------------- smem layout (bytes); bf16 tiles, row stride 144 B --------
#define SM_FH   0        // f [g][e] 128x64 (B operand of S; A-frag source)
#define SM_FL   18432
#define SM_MH   36864    // M tile [e][a]   } contiguous 55296B block copied
#define SM_ML   46080    //                 } raw from g_wt[h]
#define SM_WVH  55296    // Wv tile [e][a]
#define SM_WVL  64512
#define SM_RH   73728    // res_w slice tile [e][a]
#define SM_RL   82944
#define SM_VH   92160    // v [g][a] 128x64
#define SM_VL   110592
#define SMEM_BYTES 129024

// Pre-converted weight tiles: per head [MH][ML][WVH][WVL][RH][RL], 6*9216 B.
__device__ uint4 g_wt[H_][3456];

// ---------------- PTX helpers ----------------------------------------------
__device__ __forceinline__ uint32_t smem_u32(const void* p) {
    uint32_t a;
    asm("{ .reg .u64 t; cvta.to.shared.u64 t, %1; cvt.u32.u64 %0, t; }"
        : "=r"(a) : "l"(p));
    return a;
}
__device__ __forceinline__ void ldsm4(uint32_t addr, uint32_t r[4]) {
    asm volatile("ldmatrix.sync.aligned.m8n8.x4.shared.b16 {%0,%1,%2,%3}, [%4];"
                 : "=r"(r[0]), "=r"(r[1]), "=r"(r[2]), "=r"(r[3]) : "r"(addr));
}
__device__ __forceinline__ void ldsm4t(uint32_t addr, uint32_t r[4]) {
    asm volatile("ldmatrix.sync.aligned.m8n8.x4.trans.shared.b16 {%0,%1,%2,%3}, [%4];"
                 : "=r"(r[0]), "=r"(r[1]), "=r"(r[2]), "=r"(r[3]) : "r"(addr));
}
__device__ __forceinline__ void mma16816(float d[4], const uint32_t a[4],
                                         uint32_t b0, uint32_t b1) {
    asm("mma.sync.aligned.m16n8k16.row.col.f32.bf16.bf16.f32 "
        "{%0,%1,%2,%3}, {%4,%5,%6,%7}, {%8,%9}, {%0,%1,%2,%3};"
        : "+f"(d[0]), "+f"(d[1]), "+f"(d[2]), "+f"(d[3])
        : "r"(a[0]), "r"(a[1]), "r"(a[2]), "r"(a[3]), "r"(b0), "r"(b1));
}
// 12 MMAs (3-term hi/lo for an n-tile PAIR) round-robin over 4 independent
// accumulators: each acc re-issued every 4 MMAs -> no D->D latency stall.
// Per-acc term order (ah*bh, ah*bl, al*bh) is unchanged vs mma3.
__device__ __forceinline__ void mma12(float A0[4], float A1[4],
                                      float A2[4], float A3[4],
                                      const uint32_t ah[4], const uint32_t al[4],
                                      const uint32_t b0h[4], const uint32_t b0l[4],
                                      const uint32_t b1h[4], const uint32_t b1l[4]) {
    mma16816(A0, ah, b0h[0], b0h[1]);
    mma16816(A2, ah, b1h[0], b1h[1]);
    mma16816(A1, ah, b0h[2], b0h[3]);
    mma16816(A3, ah, b1h[2], b1h[3]);
    mma16816(A0, ah, b0l[0], b0l[1]);
    mma16816(A2, ah, b1l[0], b1l[1]);
    mma16816(A1, ah, b0l[2], b0l[3]);
    mma16816(A3, ah, b1l[2], b1l[3]);
    mma16816(A0, al, b0h[0], b0h[1]);
    mma16816(A2, al, b1h[0], b1h[1]);
    mma16816(A1, al, b0h[2], b0h[3]);
    mma16816(A3, al, b1h[2], b1h[3]);
}

// packed conversion: cvt.rn.bf16x2.f32 (first operand -> high half)
__device__ __forceinline__ uint32_t cvt_bf2(float lo_val, float hi_val) {
    uint32_t r;
    asm("cvt.rn.bf16x2.f32 %0, %1, %2;" : "=r"(r) : "f"(hi_val), "f"(lo_val));
    return r;
}
__device__ __forceinline__ uint32_t pack_hilo(float a, float b, uint32_t& lo) {
    uint32_t hi = cvt_bf2(a, b);
    float ha = __uint_as_float(hi << 16);            // bf16 -> f32 exact
    float hb = __uint_as_float(hi & 0xFFFF0000u);
    lo = cvt_bf2(a - ha, b - hb);
    return hi;
}

// =================== prep kernel: M = Wq Wk^T + tile conversion =============
__global__ __launch_bounds__(256)
void prep_kernel(const float* __restrict__ Qw, const float* __restrict__ Kw,
                 const float* __restrict__ Vw, const float* __restrict__ res_w) {
    __shared__ float4 swq[64 * 17];   // [row][j4], stride 17 float4 (68 floats)
    __shared__ float4 swk[64 * 17];
    const int h = blockIdx.x, t = threadIdx.x;
    uint8_t* dst = (uint8_t*)g_wt[h];

    for (int i = t; i < 1024; i += 256) {
        int r = i >> 4, c4 = i & 15;
        swq[r * 17 + c4] = *(const float4*)(Qw + h * 4096 + r * 64 + c4 * 4);
        swk[r * 17 + c4] = *(const float4*)(Kw + h * 4096 + r * 64 + c4 * 4);
    }
    __syncthreads();

    // M[e][a0..a0+15]: e = t&63, a0 = (t>>6)*16 (swk reads broadcast in-warp)
    {
        const int e = t & 63, a0 = (t >> 6) << 4;
        float4 q4[16];
        #pragma unroll
        for (int j4 = 0; j4 < 16; j4++) q4[j4] = swq[e * 17 + j4];
        float accs[16];
        #pragma unroll
        for (int c = 0; c < 16; c++) {
            const float4* krow = &swk[(a0 + c) * 17];
            float acc = 0.f;
            #pragma unroll
            for (int j4 = 0; j4 < 16; j4++) {
                float4 k4 = krow[j4];
                acc = fmaf(q4[j4].x, k4.x, acc);
                acc = fmaf(q4[j4].y, k4.y, acc);
                acc = fmaf(q4[j4].z, k4.z, acc);
                acc = fmaf(q4[j4].w, k4.w, acc);
            }
            accs[c] = acc;
        }
        #pragma unroll
        for (int c = 0; c < 8; c++) {
            uint32_t lo, hi = pack_hilo(accs[2 * c], accs[2 * c + 1], lo);
            uint32_t off = (uint32_t)(e * 144 + (a0 + 2 * c) * 2);
            *(uint32_t*)(dst + 0    + off) = hi;
            *(uint32_t*)(dst + 9216 + off) = lo;
        }
    }
    // Wv tile [e][a]
    for (int pi = t; pi < 2048; pi += 256) {
        int e = pi >> 5, a = (pi & 31) * 2;
        float2 v = *(const float2*)(Vw + h * 4096 + e * 64 + a);
        uint32_t lo, hi = pack_hilo(v.x, v.y, lo);
        uint32_t off = (uint32_t)(e * 144 + a * 2);
        *(uint32_t*)(dst + 18432 + off) = hi;
        *(uint32_t*)(dst + 27648 + off) = lo;
    }
    // res_w slice [e][h*64+a]
    for (int pi = t; pi < 2048; pi += 256) {
        int e = pi >> 5, a = (pi & 31) * 2;
        float2 v = *(const float2*)(res_w + e * 256 + h * 64 + a);
        uint32_t lo, hi = pack_hilo(v.x, v.y, lo);
        uint32_t off = (uint32_t)(e * 144 + a * 2);
        *(uint32_t*)(dst + 36864 + off) = hi;
        *(uint32_t*)(dst + 46080 + off) = lo;
    }
}

// =================== main kernel ============================================
__global__ __launch_bounds__(256, 1)
void attn_mma_kernel(const float* __restrict__ feature,
                     float* __restrict__ out) {
    extern __shared__ char smem[];
    const uint32_t sb = smem_u32(smem);
    const int t = threadIdx.x;
    const int w = t >> 5, l = t & 31;
    const int grp = l >> 2, qt = l & 3;      // C/A-fragment coords
    const int lr = l & 7, lm = l >> 3;       // ldmatrix lane coords
    const int b = blockIdx.x >> 2, h = blockIdx.x & 3;
    const int r0 = w * 16;                   // warp's output row base

    // ======== Phase 0: f -> smem hi/lo tile; weight tiles raw copy =========
    {
        const float4* fg = (const float4*)(feature + (size_t)b * (F_ * E_));
        #pragma unroll
        for (int it = 0; it < 8; it++) {
            int i = t + it * 256;
            float4 v = fg[i];
            int row = i >> 4, c4 = (i & 15) << 2;
            uint32_t lo0, lo1;
            uint32_t h0 = pack_hilo(v.x, v.y, lo0);
            uint32_t h1 = pack_hilo(v.z, v.w, lo1);
            uint32_t off = (uint32_t)(row * 144 + (c4 << 1));
            *(uint2*)(smem + SM_FH + off) = make_uint2(h0, h1);
            *(uint2*)(smem + SM_FL + off) = make_uint2(lo0, lo1);
        }
        const uint4* src = g_wt[h];
        uint4* dstw = (uint4*)(smem + SM_MH);
        #pragma unroll 2
        for (int i = t; i < 3456; i += 256) dstw[i] = src[i];
    }
    __syncthreads();

    // A-frag loader for f (16 rows at r0) from SM_FH/SM_FL
    auto load_f = [&](uint32_t fh[4][4], uint32_t fl[4][4]) {
        #pragma unroll
        for (int ks = 0; ks < 4; ks++) {
            uint32_t a_rel = (uint32_t)((r0 + lr + ((lm & 1) << 3)) * 144 +
                                        (ks << 5) + ((lm >> 1) << 4));
            ldsm4(sb + SM_FH + a_rel, fh[ks]);
            ldsm4(sb + SM_FL + a_rel, fl[ks]);
        }
    };
    // GEMM: A-frags (4 k-chunks) x B [K=64][N=64] (.trans), 4-way acc interleave
    auto gemmA = [&](const uint32_t ah[4][4], const uint32_t al[4][4],
                     uint32_t bh_off, uint32_t bl_off, float acc[8][4]) {
        #pragma unroll
        for (int ks = 0; ks < 4; ks++) {
            #pragma unroll
            for (int pp = 0; pp < 4; pp += 2) {
                uint32_t b0h[4], b0l[4], b1h[4], b1l[4];
                uint32_t rel0 = (uint32_t)(((ks << 4) + lr + ((lm & 1) << 3)) * 144 +
                                           (pp << 5) + ((lm >> 1) << 4));
                ldsm4t(sb + bh_off + rel0, b0h);
                ldsm4t(sb + bl_off + rel0, b0l);
                ldsm4t(sb + bh_off + rel0 + 32, b1h);
                ldsm4t(sb + bl_off + rel0 + 32, b1l);
                mma12(acc[2 * pp], acc[2 * pp + 1], acc[2 * pp + 2], acc[2 * pp + 3],
                      ah[ks], al[ks], b0h, b0l, b1h, b1l);
            }
        }
    };
    auto to_frag4 = [&](const float acc[8][4], uint32_t oh[4][4], uint32_t ol[4][4]) {
        #pragma unroll
        for (int ks = 0; ks < 4; ks++) {
            oh[ks][0] = pack_hilo(acc[2 * ks][0],     acc[2 * ks][1],     ol[ks][0]);
            oh[ks][1] = pack_hilo(acc[2 * ks][2],     acc[2 * ks][3],     ol[ks][1]);
            oh[ks][2] = pack_hilo(acc[2 * ks + 1][0], acc[2 * ks + 1][1], ol[ks][2]);
            oh[ks][3] = pack_hilo(acc[2 * ks + 1][2], acc[2 * ks + 1][3], ol[ks][3]);
        }
    };
    auto store_hilo = [&](const float acc[8][4], int oh, int ol) {
        #pragma unroll
        for (int i = 0; i < 8; i++) {
            int cbyte = (((i << 3) + (qt << 1)) << 1);
            uint32_t lo;
            uint32_t hi = pack_hilo(acc[i][0], acc[i][1], lo);
            *(uint32_t*)(smem + oh + (r0 + grp) * 144 + cbyte) = hi;
            *(uint32_t*)(smem + ol + (r0 + grp) * 144 + cbyte) = lo;
            hi = pack_hilo(acc[i][2], acc[i][3], lo);
            *(uint32_t*)(smem + oh + (r0 + grp + 8) * 144 + cbyte) = hi;
            *(uint32_t*)(smem + ol + (r0 + grp + 8) * 144 + cbyte) = lo;
        }
    };

    // ================= Phase 1: qm = f@M,  v = f@Wv  (f-frags scoped) ======
    uint32_t qmh[4][4], qml[4][4];
    {
        uint32_t fh[4][4], fl[4][4];
        load_f(fh, fl);
        {
            float acc[8][4] = {};
            gemmA(fh, fl, SM_MH, SM_ML, acc);
            to_frag4(acc, qmh, qml);         // qm stays in registers
        }
        {
            float acc[8][4] = {};
            gemmA(fh, fl, SM_WVH, SM_WVL, acc);
            store_hilo(acc, SM_VH, SM_VL);   // v needed by all warps -> smem
        }
    }
    __syncthreads();

    // ================= Phase 2: S = qm @ f^T (16 x 128 per warp) ===========
    float sacc[16][4] = {};
    #pragma unroll
    for (int ks = 0; ks < 4; ks++) {
        #pragma unroll
        for (int pp = 0; pp < 8; pp += 2) {
            uint32_t b0h[4], b0l[4], b1h[4], b1l[4];
            uint32_t rel0 = (uint32_t)(((pp << 4) + lr + ((lm >> 1) << 3)) * 144 +
                                       (ks << 5) + ((lm & 1) << 4));
            ldsm4(sb + SM_FH + rel0, b0h);
            ldsm4(sb + SM_FL + rel0, b0l);
            ldsm4(sb + SM_FH + rel0 + 16 * 144, b1h);
            ldsm4(sb + SM_FL + rel0 + 16 * 144, b1l);
            mma12(sacc[2 * pp], sacc[2 * pp + 1], sacc[2 * pp + 2], sacc[2 * pp + 3],
                  qmh[ks], qml[ks], b0h, b0l, b1h, b1l);
        }
    }

    // ================= Phase 3: softmax in registers =======================
    float invA, invB;
    {
        float mA = -3.402823466e38f, mB = -3.402823466e38f;
        #pragma unroll
        for (int i = 0; i < 16; i++) {
            mA = fmaxf(mA, fmaxf(sacc[i][0], sacc[i][1]));
            mB = fmaxf(mB, fmaxf(sacc[i][2], sacc[i][3]));
        }
        mA = fmaxf(mA, __shfl_xor_sync(0xFFFFFFFFu, mA, 1));
        mA = fmaxf(mA, __shfl_xor_sync(0xFFFFFFFFu, mA, 2));
        mB = fmaxf(mB, __shfl_xor_sync(0xFFFFFFFFu, mB, 1));
        mB = fmaxf(mB, __shfl_xor_sync(0xFFFFFFFFu, mB, 2));
        float sA = 0.f, sB = 0.f;
        #pragma unroll
        for (int i = 0; i < 16; i++) {
            sacc[i][0] = __expf(sacc[i][0] - mA);
            sacc[i][1] = __expf(sacc[i][1] - mA);
            sacc[i][2] = __expf(sacc[i][2] - mB);
            sacc[i][3] = __expf(sacc[i][3] - mB);
            sA += sacc[i][0] + sacc[i][1];
            sB += sacc[i][2] + sacc[i][3];
        }
        sA += __shfl_xor_sync(0xFFFFFFFFu, sA, 1);
        sA += __shfl_xor_sync(0xFFFFFFFFu, sA, 2);
        sB += __shfl_xor_sync(0xFFFFFFFFu, sB, 1);
        sB += __shfl_xor_sync(0xFFFFFFFFu, sB, 2);
        invA = 1.0f / sA;
        invB = 1.0f / sB;
    }

    // P (unnormalized) -> register A-fragments, 8 k-chunks
    uint32_t ph[8][4], pl[8][4];
    #pragma unroll
    for (int ks = 0; ks < 8; ks++) {
        ph[ks][0] = pack_hilo(sacc[2 * ks][0],     sacc[2 * ks][1],     pl[ks][0]);
        ph[ks][1] = pack_hilo(sacc[2 * ks][2],     sacc[2 * ks][3],     pl[ks][1]);
        ph[ks][2] = pack_hilo(sacc[2 * ks + 1][0], sacc[2 * ks + 1][1], pl[ks][2]);
        ph[ks][3] = pack_hilo(sacc[2 * ks + 1][2], sacc[2 * ks + 1][3], pl[ks][3]);
    }

    // ================= Phase 4: em = P @ v  (K=128) ========================
    float eacc[8][4] = {};
    #pragma unroll
    for (int ks = 0; ks < 8; ks++) {
        #pragma unroll
        for (int pp = 0; pp < 4; pp += 2) {
            uint32_t b0h[4], b0l[4], b1h[4], b1l[4];
            uint32_t rel0 = (uint32_t)(((ks << 4) + lr + ((lm & 1) << 3)) * 144 +
                                       (pp << 5) + ((lm >> 1) << 4));
            ldsm4t(sb + SM_VH + rel0, b0h);
            ldsm4t(sb + SM_VL + rel0, b0l);
            ldsm4t(sb + SM_VH + rel0 + 32, b1h);
            ldsm4t(sb + SM_VL + rel0 + 32, b1l);
            mma12(eacc[2 * pp], eacc[2 * pp + 1], eacc[2 * pp + 2], eacc[2 * pp + 3],
                  ph[ks], pl[ks], b0h, b0l, b1h, b1l);
        }
    }

    // ================= Phase 5: res = f @ res_w slice ======================
    float racc[8][4] = {};
    {
        uint32_t fh[4][4], fl[4][4];
        load_f(fh, fl);                      // reload (f-frags were scoped out)
        gemmA(fh, fl, SM_RH, SM_RL, racc);
    }

    // ================= Phase 6: epilogue relu(em/sum + res) ================
    {
        #pragma unroll
        for (int i = 0; i < 8; i++) {
            int c = h * A_ + (i << 3) + (qt << 1);
            float2 o;
            o.x = fmaxf(fmaf(eacc[i][0], invA, racc[i][0]), 0.f);
            o.y = fmaxf(fmaf(eacc[i][1], invA, racc[i][1]), 0.f);
            *(float2*)(out + ((size_t)(b * F_) + r0 + grp) * (H_ * A_) + c) = o;
            o.x = fmaxf(fmaf(eacc[i][2], invB, racc[i][2]), 0.f);
            o.y = fmaxf(fmaf(eacc[i][3], invB, racc[i][3]), 0.f);
            *(float2*)(out + ((size_t)(b * F_) + r0 + grp + 8) * (H_ * A_) + c) = o;
        }
    }
}

extern "C" void kernel_launch(void* const* d_in, const int* in_sizes, int n_in,
                              void* d_out, int out_size) {
    const float* feature = (const float*)d_in[0];
    const float* Qw      = (const float*)d_in[1];
    const float* Kw      = (const float*)d_in[2];
    const float* Vw      = (const float*)d_in[3];
    const float* res_w   = (const float*)d_in[4];
    float* out = (float*)d_out;

    prep_kernel<<<H_, 256>>>(Qw, Kw, Vw, res_w);

    cudaFuncSetAttribute(attn_mma_kernel,
                         cudaFuncAttributeMaxDynamicSharedMemorySize, SMEM_BYTES);
    attn_mma_kernel<<<B_ * H_, 256, SMEM_BYTES>>>(feature, out);
}

// round 17
// speedup vs baseline: 1.2500x; 1.2330x over previous
#include <cuda_runtime.h>
#include <cuda_bf16.h>
#include <cstdint>

// AttentionLayer: B=2048, F=128, E=64, H=4, A=64
//   out[b,f,h*64+a] = relu( softmax(q k^T) v + (feature @ res_w)[:, h*64:] )
//
// R17: persistent-CTA kernel. Grid 608 = 152 SMs x 4 heads; CTA owns head
// h = blockIdx&3, loops b with stride 152. Prologue (once per CTA): stage
// Wq/Wk, compute M = Wq Wk^T in exact fp32, convert M/Wv/res-slice to hi/lo
// bf16 tiles. Per tile: cp.async-prefetched f (issued during previous tile's
// compute), then R16's GEMM phases unchanged (3-term hi/lo bf16 mma.sync).

#define B_ 2048
#define F_ 128
#define E_ 64
#define H_ 4
#define A_ 64
#define BSTRIDE_ 152
#define GRID_ (BSTRIDE_ * H_)

// ---------------- smem layout (bytes); bf16 tiles, row stride 144 B --------
#define SM_FH    0        // f [g][e] 128x64 (B operand of S; A-frag source)
#define SM_FL    18432
#define SM_MH    36864    // M tile [e][a]
#define SM_ML    46080
#define SM_WVH   55296    // Wv tile [e][a]
#define SM_WVL   64512
#define SM_RH    73728    // res_w slice tile [e][a]
#define SM_RL    82944
#define SM_VH    92160    // v [g][a] 128x64
#define SM_VL    110592
#define SM_STAGE 129024   // raw staging: f fp32 (32768B) / Wq+Wk padded (34816B)
#define SMEM_BYTES (129024 + 34816)

// ---------------- PTX helpers ----------------------------------------------
__device__ __forceinline__ uint32_t smem_u32(const void* p) {
    uint32_t a;
    asm("{ .reg .u64 t; cvta.to.shared.u64 t, %1; cvt.u32.u64 %0, t; }"
        : "=r"(a) : "l"(p));
    return a;
}
__device__ __forceinline__ void ldsm4(uint32_t addr, uint32_t r[4]) {
    asm volatile("ldmatrix.sync.aligned.m8n8.x4.shared.b16 {%0,%1,%2,%3}, [%4];"
                 : "=r"(r[0]), "=r"(r[1]), "=r"(r[2]), "=r"(r[3]) : "r"(addr));
}
__device__ __forceinline__ void ldsm4t(uint32_t addr, uint32_t r[4]) {
    asm volatile("ldmatrix.sync.aligned.m8n8.x4.trans.shared.b16 {%0,%1,%2,%3}, [%4];"
                 : "=r"(r[0]), "=r"(r[1]), "=r"(r[2]), "=r"(r[3]) : "r"(addr));
}
__device__ __forceinline__ void mma16816(float d[4], const uint32_t a[4],
                                         uint32_t b0, uint32_t b1) {
    asm("mma.sync.aligned.m16n8k16.row.col.f32.bf16.bf16.f32 "
        "{%0,%1,%2,%3}, {%4,%5,%6,%7}, {%8,%9}, {%0,%1,%2,%3};"
        : "+f"(d[0]), "+f"(d[1]), "+f"(d[2]), "+f"(d[3])
        : "r"(a[0]), "r"(a[1]), "r"(a[2]), "r"(a[3]), "r"(b0), "r"(b1));
}
// 12 MMAs (3-term hi/lo for an n-tile PAIR) over 4 independent accumulators.
__device__ __forceinline__ void mma12(float A0[4], float A1[4],
                                      float A2[4], float A3[4],
                                      const uint32_t ah[4], const uint32_t al[4],
                                      const uint32_t b0h[4], const uint32_t b0l[4],
                                      const uint32_t b1h[4], const uint32_t b1l[4]) {
    mma16816(A0, ah, b0h[0], b0h[1]);
    mma16816(A2, ah, b1h[0], b1h[1]);
    mma16816(A1, ah, b0h[2], b0h[3]);
    mma16816(A3, ah, b1h[2], b1h[3]);
    mma16816(A0, ah, b0l[0], b0l[1]);
    mma16816(A2, ah, b1l[0], b1l[1]);
    mma16816(A1, ah, b0l[2], b0l[3]);
    mma16816(A3, ah, b1l[2], b1l[3]);
    mma16816(A0, al, b0h[0], b0h[1]);
    mma16816(A2, al, b1h[0], b1h[1]);
    mma16816(A1, al, b0h[2], b0h[3]);
    mma16816(A3, al, b1h[2], b1h[3]);
}

// packed conversion: cvt.rn.bf16x2.f32 (first operand -> high half)
__device__ __forceinline__ uint32_t cvt_bf2(float lo_val, float hi_val) {
    uint32_t r;
    asm("cvt.rn.bf16x2.f32 %0, %1, %2;" : "=r"(r) : "f"(hi_val), "f"(lo_val));
    return r;
}
__device__ __forceinline__ uint32_t pack_hilo(float a, float b, uint32_t& lo) {
    uint32_t hi = cvt_bf2(a, b);
    float ha = __uint_as_float(hi << 16);            // bf16 -> f32 exact
    float hb = __uint_as_float(hi & 0xFFFF0000u);
    lo = cvt_bf2(a - ha, b - hb);
    return hi;
}

__device__ __forceinline__ void cp_async16(uint32_t smem_dst, const void* gmem_src) {
    asm volatile("cp.async.cg.shared.global [%0], [%1], 16;"
                 :: "r"(smem_dst), "l"(gmem_src));
}

// =================== persistent main kernel =================================
__global__ __launch_bounds__(256, 1)
void attn_mma_kernel(const float* __restrict__ feature,
                     const float* __restrict__ Qw,
                     const float* __restrict__ Kw,
                     const float* __restrict__ Vw,
                     const float* __restrict__ res_w,
                     float* __restrict__ out) {
    extern __shared__ char smem[];
    const uint32_t sb = smem_u32(smem);
    const int t = threadIdx.x;
    const int w = t >> 5, l = t & 31;
    const int grp = l >> 2, qt = l & 3;      // C/A-fragment coords
    const int lr = l & 7, lm = l >> 3;       // ldmatrix lane coords
    const int h = blockIdx.x & 3;
    const int bid = blockIdx.x >> 2;         // b0 in [0,152)
    const int r0 = w * 16;                   // warp's output row base

    // ================== Prologue: per-CTA weight setup =====================
    {
        // stage Wq,Wk as float4 rows with stride 17 (bank-conflict-free)
        float4* swq = (float4*)(smem + SM_STAGE);
        float4* swk = swq + 1088;
        #pragma unroll
        for (int it = 0; it < 4; it++) {
            int i = t + it * 256;            // i in [0,1024): r = i>>4, j4 = i&15
            int r = i >> 4, j4 = i & 15;
            swq[r * 17 + j4] = *(const float4*)(Qw + h * 4096 + r * 64 + j4 * 4);
            swk[r * 17 + j4] = *(const float4*)(Kw + h * 4096 + r * 64 + j4 * 4);
        }
        __syncthreads();

        // M[e][a0..a0+15] = (Wq Wk^T) in exact fp32; write hi/lo tile
        {
            const int e = t & 63, a0 = (t >> 6) << 4;
            float4 q4[16];
            #pragma unroll
            for (int j4 = 0; j4 < 16; j4++) q4[j4] = swq[e * 17 + j4];
            float accs[16];
            #pragma unroll
            for (int c = 0; c < 16; c++) {
                const float4* krow = &swk[(a0 + c) * 17];
                float acc = 0.f;
                #pragma unroll
                for (int j4 = 0; j4 < 16; j4++) {
                    float4 k4 = krow[j4];
                    acc = fmaf(q4[j4].x, k4.x, acc);
                    acc = fmaf(q4[j4].y, k4.y, acc);
                    acc = fmaf(q4[j4].z, k4.z, acc);
                    acc = fmaf(q4[j4].w, k4.w, acc);
                }
                accs[c] = acc;
            }
            #pragma unroll
            for (int c = 0; c < 8; c++) {
                uint32_t lo, hi = pack_hilo(accs[2 * c], accs[2 * c + 1], lo);
                uint32_t off = (uint32_t)(e * 144 + (a0 + 2 * c) * 2);
                *(uint32_t*)(smem + SM_MH + off) = hi;
                *(uint32_t*)(smem + SM_ML + off) = lo;
            }
        }
        // Wv tile [e][a]
        #pragma unroll
        for (int pi = t; pi < 2048; pi += 256) {
            int e = pi >> 5, a = (pi & 31) * 2;
            float2 v = *(const float2*)(Vw + h * 4096 + e * 64 + a);
            uint32_t lo, hi = pack_hilo(v.x, v.y, lo);
            uint32_t off = (uint32_t)(e * 144 + a * 2);
            *(uint32_t*)(smem + SM_WVH + off) = hi;
            *(uint32_t*)(smem + SM_WVL + off) = lo;
        }
        // res_w slice [e][h*64+a]
        #pragma unroll
        for (int pi = t; pi < 2048; pi += 256) {
            int e = pi >> 5, a = (pi & 31) * 2;
            float2 v = *(const float2*)(res_w + e * 256 + h * 64 + a);
            uint32_t lo, hi = pack_hilo(v.x, v.y, lo);
            uint32_t off = (uint32_t)(e * 144 + a * 2);
            *(uint32_t*)(smem + SM_RH + off) = hi;
            *(uint32_t*)(smem + SM_RL + off) = lo;
        }
        __syncthreads();   // weights ready; stage free for f prefetch
    }

    // ---- helpers (identical math to R16) ----------------------------------
    auto prefetch_f = [&](int bb) {
        const uint4* src = (const uint4*)(feature + (size_t)bb * (F_ * E_));
        #pragma unroll
        for (int it = 0; it < 8; it++) {
            int i = t + it * 256;
            cp_async16(sb + SM_STAGE + i * 16, src + i);
        }
        asm volatile("cp.async.commit_group;" ::: "memory");
    };
    auto load_f = [&](uint32_t fh[4][4], uint32_t fl[4][4]) {
        #pragma unroll
        for (int ks = 0; ks < 4; ks++) {
            uint32_t a_rel = (uint32_t)((r0 + lr + ((lm & 1) << 3)) * 144 +
                                        (ks << 5) + ((lm >> 1) << 4));
            ldsm4(sb + SM_FH + a_rel, fh[ks]);
            ldsm4(sb + SM_FL + a_rel, fl[ks]);
        }
    };
    auto gemmA = [&](const uint32_t ah[4][4], const uint32_t al[4][4],
                     uint32_t bh_off, uint32_t bl_off, float acc[8][4]) {
        #pragma unroll
        for (int ks = 0; ks < 4; ks++) {
            #pragma unroll
            for (int pp = 0; pp < 4; pp += 2) {
                uint32_t b0h[4], b0l[4], b1h[4], b1l[4];
                uint32_t rel0 = (uint32_t)(((ks << 4) + lr + ((lm & 1) << 3)) * 144 +
                                           (pp << 5) + ((lm >> 1) << 4));
                ldsm4t(sb + bh_off + rel0, b0h);
                ldsm4t(sb + bl_off + rel0, b0l);
                ldsm4t(sb + bh_off + rel0 + 32, b1h);
                ldsm4t(sb + bl_off + rel0 + 32, b1l);
                mma12(acc[2 * pp], acc[2 * pp + 1], acc[2 * pp + 2], acc[2 * pp + 3],
                      ah[ks], al[ks], b0h, b0l, b1h, b1l);
            }
        }
    };
    auto to_frag4 = [&](const float acc[8][4], uint32_t oh[4][4], uint32_t ol[4][4]) {
        #pragma unroll
        for (int ks = 0; ks < 4; ks++) {
            oh[ks][0] = pack_hilo(acc[2 * ks][0],     acc[2 * ks][1],     ol[ks][0]);
            oh[ks][1] = pack_hilo(acc[2 * ks][2],     acc[2 * ks][3],     ol[ks][1]);
            oh[ks][2] = pack_hilo(acc[2 * ks + 1][0], acc[2 * ks + 1][1], ol[ks][2]);
            oh[ks][3] = pack_hilo(acc[2 * ks + 1][2], acc[2 * ks + 1][3], ol[ks][3]);
        }
    };
    auto store_hilo = [&](const float acc[8][4], int oh, int ol) {
        #pragma unroll
        for (int i = 0; i < 8; i++) {
            int cbyte = (((i << 3) + (qt << 1)) << 1);
            uint32_t lo;
            uint32_t hi = pack_hilo(acc[i][0], acc[i][1], lo);
            *(uint32_t*)(smem + oh + (r0 + grp) * 144 + cbyte) = hi;
            *(uint32_t*)(smem + ol + (r0 + grp) * 144 + cbyte) = lo;
            hi = pack_hilo(acc[i][2], acc[i][3], lo);
            *(uint32_t*)(smem + oh + (r0 + grp + 8) * 144 + cbyte) = hi;
            *(uint32_t*)(smem + ol + (r0 + grp + 8) * 144 + cbyte) = lo;
        }
    };

    // ================== persistent loop over batches =======================
    prefetch_f(bid);
    for (int b = bid; b < B_; b += BSTRIDE_) {
        // ---- f(b) arrives in stage; convert to hi/lo bf16 tile ----
        asm volatile("cp.async.wait_group 0;" ::: "memory");
        __syncthreads();   // stage ready; all warps done with previous tile
        {
            const float4* st4 = (const float4*)(smem + SM_STAGE);
            #pragma unroll
            for (int it = 0; it < 8; it++) {
                int i = t + it * 256;
                float4 v = st4[i];
                int row = i >> 4, c4 = (i & 15) << 2;
                uint32_t lo0, lo1;
                uint32_t h0 = pack_hilo(v.x, v.y, lo0);
                uint32_t h1 = pack_hilo(v.z, v.w, lo1);
                uint32_t off = (uint32_t)(row * 144 + (c4 << 1));
                *(uint2*)(smem + SM_FH + off) = make_uint2(h0, h1);
                *(uint2*)(smem + SM_FL + off) = make_uint2(lo0, lo1);
            }
        }
        __syncthreads();   // FH/FL ready; stage reads complete
        const int nb = b + BSTRIDE_;
        if (nb < B_) prefetch_f(nb);   // overlaps all compute below

        // ============ Phase 1: qm = f@M,  v = f@Wv  (f-frags scoped) =======
        uint32_t qmh[4][4], qml[4][4];
        {
            uint32_t fh[4][4], fl[4][4];
            load_f(fh, fl);
            {
                float acc[8][4] = {};
                gemmA(fh, fl, SM_MH, SM_ML, acc);
                to_frag4(acc, qmh, qml);
            }
            {
                float acc[8][4] = {};
                gemmA(fh, fl, SM_WVH, SM_WVL, acc);
                store_hilo(acc, SM_VH, SM_VL);
            }
        }
        __syncthreads();

        // ============ Phase 2: S = qm @ f^T (16 x 128 per warp) ============
        float sacc[16][4] = {};
        #pragma unroll
        for (int ks = 0; ks < 4; ks++) {
            #pragma unroll
            for (int pp = 0; pp < 8; pp += 2) {
                uint32_t b0h[4], b0l[4], b1h[4], b1l[4];
                uint32_t rel0 = (uint32_t)(((pp << 4) + lr + ((lm >> 1) << 3)) * 144 +
                                           (ks << 5) + ((lm & 1) << 4));
                ldsm4(sb + SM_FH + rel0, b0h);
                ldsm4(sb + SM_FL + rel0, b0l);
                ldsm4(sb + SM_FH + rel0 + 16 * 144, b1h);
                ldsm4(sb + SM_FL + rel0 + 16 * 144, b1l);
                mma12(sacc[2 * pp], sacc[2 * pp + 1], sacc[2 * pp + 2], sacc[2 * pp + 3],
                      qmh[ks], qml[ks], b0h, b0l, b1h, b1l);
            }
        }

        // ============ Phase 3: softmax in registers ========================
        float invA, invB;
        {
            float mA = -3.402823466e38f, mB = -3.402823466e38f;
            #pragma unroll
            for (int i = 0; i < 16; i++) {
                mA = fmaxf(mA, fmaxf(sacc[i][0], sacc[i][1]));
                mB = fmaxf(mB, fmaxf(sacc[i][2], sacc[i][3]));
            }
            mA = fmaxf(mA, __shfl_xor_sync(0xFFFFFFFFu, mA, 1));
            mA = fmaxf(mA, __shfl_xor_sync(0xFFFFFFFFu, mA, 2));
            mB = fmaxf(mB, __shfl_xor_sync(0xFFFFFFFFu, mB, 1));
            mB = fmaxf(mB, __shfl_xor_sync(0xFFFFFFFFu, mB, 2));
            float sA = 0.f, sB = 0.f;
            #pragma unroll
            for (int i = 0; i < 16; i++) {
                sacc[i][0] = __expf(sacc[i][0] - mA);
                sacc[i][1] = __expf(sacc[i][1] - mA);
                sacc[i][2] = __expf(sacc[i][2] - mB);
                sacc[i][3] = __expf(sacc[i][3] - mB);
                sA += sacc[i][0] + sacc[i][1];
                sB += sacc[i][2] + sacc[i][3];
            }
            sA += __shfl_xor_sync(0xFFFFFFFFu, sA, 1);
            sA += __shfl_xor_sync(0xFFFFFFFFu, sA, 2);
            sB += __shfl_xor_sync(0xFFFFFFFFu, sB, 1);
            sB += __shfl_xor_sync(0xFFFFFFFFu, sB, 2);
            invA = 1.0f / sA;
            invB = 1.0f / sB;
        }

        // P (unnormalized) -> register A-fragments, 8 k-chunks
        uint32_t ph[8][4], pl[8][4];
        #pragma unroll
        for (int ks = 0; ks < 8; ks++) {
            ph[ks][0] = pack_hilo(sacc[2 * ks][0],     sacc[2 * ks][1],     pl[ks][0]);
            ph[ks][1] = pack_hilo(sacc[2 * ks][2],     sacc[2 * ks][3],     pl[ks][1]);
            ph[ks][2] = pack_hilo(sacc[2 * ks + 1][0], sacc[2 * ks + 1][1], pl[ks][2]);
            ph[ks][3] = pack_hilo(sacc[2 * ks + 1][2], sacc[2 * ks + 1][3], pl[ks][3]);
        }

        // ============ Phase 4: em = P @ v  (K=128) =========================
        float eacc[8][4] = {};
        #pragma unroll
        for (int ks = 0; ks < 8; ks++) {
            #pragma unroll
            for (int pp = 0; pp < 4; pp += 2) {
                uint32_t b0h[4], b0l[4], b1h[4], b1l[4];
                uint32_t rel0 = (uint32_t)(((ks << 4) + lr + ((lm & 1) << 3)) * 144 +
                                           (pp << 5) + ((lm >> 1) << 4));
                ldsm4t(sb + SM_VH + rel0, b0h);
                ldsm4t(sb + SM_VL + rel0, b0l);
                ldsm4t(sb + SM_VH + rel0 + 32, b1h);
                ldsm4t(sb + SM_VL + rel0 + 32, b1l);
                mma12(eacc[2 * pp], eacc[2 * pp + 1], eacc[2 * pp + 2], eacc[2 * pp + 3],
                      ph[ks], pl[ks], b0h, b0l, b1h, b1l);
            }
        }

        // ============ Phase 5: res = f @ res_w slice =======================
        float racc[8][4] = {};
        {
            uint32_t fh[4][4], fl[4][4];
            load_f(fh, fl);
            gemmA(fh, fl, SM_RH, SM_RL, racc);
        }

        // ============ Phase 6: epilogue relu(em/sum + res) =================
        #pragma unroll
        for (int i = 0; i < 8; i++) {
            int c = h * A_ + (i << 3) + (qt << 1);
            float2 o;
            o.x = fmaxf(fmaf(eacc[i][0], invA, racc[i][0]), 0.f);
            o.y = fmaxf(fmaf(eacc[i][1], invA, racc[i][1]), 0.f);
            *(float2*)(out + ((size_t)(b * F_) + r0 + grp) * (H_ * A_) + c) = o;
            o.x = fmaxf(fmaf(eacc[i][2], invB, racc[i][2]), 0.f);
            o.y = fmaxf(fmaf(eacc[i][3], invB, racc[i][3]), 0.f);
            *(float2*)(out + ((size_t)(b * F_) + r0 + grp + 8) * (H_ * A_) + c) = o;
        }
    }
}

extern "C" void kernel_launch(void* const* d_in, const int* in_sizes, int n_in,
                              void* d_out, int out_size) {
    const float* feature = (const float*)d_in[0];
    const float* Qw      = (const float*)d_in[1];
    const float* Kw      = (const float*)d_in[2];
    const float* Vw      = (const float*)d_in[3];
    const float* res_w   = (const float*)d_in[4];
    float* out = (float*)d_out;

    cudaFuncSetAttribute(attn_mma_kernel,
                         cudaFuncAttributeMaxDynamicSharedMemorySize, SMEM_BYTES);
    attn_mma_kernel<<<GRID_, 256, SMEM_BYTES>>>(feature, Qw, Kw, Vw, res_w, out);
}